// round 14
// baseline (speedup 1.0000x reference)
#include <cuda_runtime.h>
#include <cuda_bf16.h>
#include <cuda_fp16.h>
#include <math.h>

// ---------------------------------------------------------------------------
// Problem constants
// ---------------------------------------------------------------------------
#define BATCH   16384
#define NHIST   50
#define DIM     128
#define NITEMS  100000

// ---------------------------------------------------------------------------
// Scratch (static device globals)
// ---------------------------------------------------------------------------
__device__ __nv_bfloat16 g_KV[NITEMS * 256];   // per item: 128 bf16 K | 128 bf16 V
__device__ __nv_bfloat16 g_Qg [BATCH * DIM];
__device__ __nv_bfloat16 g_Q2 [BATCH * DIM];
__device__ __nv_bfloat16 g_K0 [BATCH * DIM];
__device__ float g_V0 [BATCH * DIM];
__device__ float g_Y  [BATCH * DIM];
// bf16 weight splits, transposed to [n][k]: slot 2*w = hi, 2*w+1 = lo
// w: 0=gat_wq 1=gat_wk 2=gat_wv 3=gat_wo 4=sem_wq 5=sem_wk 6=sem_wv 7=sem_wo
__device__ unsigned short g_W4[16][DIM * DIM];
// fp16 transposed weights for the item GEMM: 0=gat_wk, 1=gat_wv
__device__ unsigned short g_Wh[2][DIM * DIM];

// ---------------------------------------------------------------------------
// helpers
// ---------------------------------------------------------------------------
__device__ __forceinline__ unsigned smem_u32(const void* p) {
    unsigned a;
    asm("{ .reg .u64 t; cvta.to.shared.u64 t, %1; cvt.u32.u64 %0, t; }"
        : "=r"(a) : "l"(p));
    return a;
}
__device__ __forceinline__ void ldm4(unsigned& r0, unsigned& r1,
                                     unsigned& r2, unsigned& r3, unsigned addr) {
    asm volatile("ldmatrix.sync.aligned.m8n8.x4.shared.b16 {%0,%1,%2,%3}, [%4];"
                 : "=r"(r0), "=r"(r1), "=r"(r2), "=r"(r3) : "r"(addr));
}
__device__ __forceinline__ void mma_bf16(float* d, const unsigned* a, const unsigned* b) {
    asm volatile("mma.sync.aligned.m16n8k16.row.col.f32.bf16.bf16.f32 "
                 "{%0,%1,%2,%3}, {%4,%5,%6,%7}, {%8,%9}, {%0,%1,%2,%3};"
                 : "+f"(d[0]), "+f"(d[1]), "+f"(d[2]), "+f"(d[3])
                 : "r"(a[0]), "r"(a[1]), "r"(a[2]), "r"(a[3]),
                   "r"(b[0]), "r"(b[1]));
}
__device__ __forceinline__ void mma_f16(float* d, const unsigned* a, const unsigned* b) {
    asm volatile("mma.sync.aligned.m16n8k16.row.col.f32.f16.f16.f32 "
                 "{%0,%1,%2,%3}, {%4,%5,%6,%7}, {%8,%9}, {%0,%1,%2,%3};"
                 : "+f"(d[0]), "+f"(d[1]), "+f"(d[2]), "+f"(d[3])
                 : "r"(a[0]), "r"(a[1]), "r"(a[2]), "r"(a[3]),
                   "r"(b[0]), "r"(b[1]));
}
// smem byte offset for (row, 8-elem 16B chunk kc): 256B rows, XOR swizzle
__device__ __forceinline__ unsigned sw_off(int row, int kc) {
    return (unsigned)(row * 256 + ((kc ^ (row & 7)) << 4));
}
// split 8 fp32 -> two uint4 of bf16 (hi, lo = residual)
__device__ __forceinline__ void split8(const float* xs, uint4& H, uint4& L) {
    unsigned hw[4], lw[4];
    #pragma unroll
    for (int j = 0; j < 4; j++) {
        __nv_bfloat16 h0 = __float2bfloat16(xs[2*j]);
        __nv_bfloat16 h1 = __float2bfloat16(xs[2*j+1]);
        __nv_bfloat16 l0 = __float2bfloat16(xs[2*j]   - __bfloat162float(h0));
        __nv_bfloat16 l1 = __float2bfloat16(xs[2*j+1] - __bfloat162float(h1));
        hw[j] = (unsigned)*(unsigned short*)&h0 | ((unsigned)*(unsigned short*)&h1 << 16);
        lw[j] = (unsigned)*(unsigned short*)&l0 | ((unsigned)*(unsigned short*)&l1 << 16);
    }
    H = make_uint4(hw[0], hw[1], hw[2], hw[3]);
    L = make_uint4(lw[0], lw[1], lw[2], lw[3]);
}
// 8 fp32 -> uint4 of fp16
__device__ __forceinline__ uint4 pack8f16(const float* xs) {
    unsigned hw[4];
    #pragma unroll
    for (int j = 0; j < 4; j++) {
        const unsigned short a = __half_as_ushort(__float2half_rn(xs[2*j]));
        const unsigned short b = __half_as_ushort(__float2half_rn(xs[2*j+1]));
        hw[j] = (unsigned)a | ((unsigned)b << 16);
    }
    return make_uint4(hw[0], hw[1], hw[2], hw[3]);
}
__device__ __forceinline__ unsigned pack_bf2(float a, float b) {
    __nv_bfloat16 x = __float2bfloat16(a), y = __float2bfloat16(b);
    return (unsigned)*(unsigned short*)&x | ((unsigned)*(unsigned short*)&y << 16);
}
// bf16x2 unpack via shift/mask
__device__ __forceinline__ float bflo(unsigned u) { return __uint_as_float(u << 16); }
__device__ __forceinline__ float bfhi(unsigned u) { return __uint_as_float(u & 0xffff0000u); }
// write a (v0,v1) pair as bf16 hi + residual lo into split A slots
__device__ __forceinline__ void store_pair_split(
    char* sm, unsigned oHi, unsigned oLo, int r, int c, float v0, float v1)
{
    const unsigned off = sw_off(r, c >> 3) + (c & 7) * 2;
    *(unsigned*)(sm + oHi + off) = pack_bf2(v0, v1);
    *(unsigned*)(sm + oLo + off) =
        pack_bf2(v0 - bfhi(pack_bf2(0.f, v0)), v1 - bfhi(pack_bf2(0.f, v1)));
}

// ===========================================================================
// Setup: transpose + split all weight matrices
// ===========================================================================
__global__ void w_setup(const float* w0, const float* w1, const float* w2,
                        const float* w3, const float* w4, const float* w5,
                        const float* w6, const float* w7)
{
    const int i = blockIdx.x * blockDim.x + threadIdx.x;
    if (i >= DIM * DIM) return;
    const float* ws[8] = {w0, w1, w2, w3, w4, w5, w6, w7};
    const int k = i >> 7, n = i & 127;
    const int dst = n * DIM + k;
    #pragma unroll
    for (int w = 0; w < 8; w++) {
        const float a = ws[w][i];
        __nv_bfloat16 h = __float2bfloat16(a);
        __nv_bfloat16 l = __float2bfloat16(a - __bfloat162float(h));
        g_W4[2*w    ][dst] = *(unsigned short*)&h;
        g_W4[2*w + 1][dst] = *(unsigned short*)&l;
    }
    g_Wh[0][dst] = __half_as_ushort(__float2half_rn(w1[i]));   // gat_wk
    g_Wh[1][dst] = __half_as_ushort(__float2half_rn(w2[i]));   // gat_wv
}

// ===========================================================================
// Shared GEMM building blocks. 8 warps (4x2), warp tile 32x64, CTA 128x128.
// ===========================================================================
template<int TERMS>
__device__ __forceinline__ void mma_loop(
    unsigned sb, unsigned oAhi, unsigned oAlo, unsigned oWhi, unsigned oWlo,
    int wm, int wn, int lane, float acc[2][8][4])
{
    #pragma unroll
    for (int i = 0; i < 2; i++)
        #pragma unroll
        for (int j = 0; j < 8; j++)
            #pragma unroll
            for (int q = 0; q < 4; q++) acc[i][j][q] = 0.f;

    #pragma unroll
    for (int ks = 0; ks < 8; ks++) {
        unsigned aH[2][4], aL[2][4], bH[8][2], bL[8][2];
        {
            const int r  = wm * 32 + (lane & 15);
            const int kc = ks * 2 + (lane >> 4);
            ldm4(aH[0][0], aH[0][1], aH[0][2], aH[0][3], sb + oAhi + sw_off(r,      kc));
            ldm4(aH[1][0], aH[1][1], aH[1][2], aH[1][3], sb + oAhi + sw_off(r + 16, kc));
            if (TERMS == 3) {
                ldm4(aL[0][0], aL[0][1], aL[0][2], aL[0][3], sb + oAlo + sw_off(r,      kc));
                ldm4(aL[1][0], aL[1][1], aL[1][2], aL[1][3], sb + oAlo + sw_off(r + 16, kc));
            }
        }
        {
            const int grp  = lane >> 3;
            const int nloc = (lane & 7) + ((grp >> 1) << 3);
            const int kc   = ks * 2 + (grp & 1);
            #pragma unroll
            for (int j = 0; j < 4; j++) {
                const int n = wn * 64 + j * 16 + nloc;
                ldm4(bH[2*j][0], bH[2*j][1], bH[2*j+1][0], bH[2*j+1][1],
                     sb + oWhi + sw_off(n, kc));
                if (TERMS == 3)
                    ldm4(bL[2*j][0], bL[2*j][1], bL[2*j+1][0], bL[2*j+1][1],
                         sb + oWlo + sw_off(n, kc));
            }
        }
        #pragma unroll
        for (int mf = 0; mf < 2; mf++)
            #pragma unroll
            for (int nf = 0; nf < 8; nf++) {
                mma_bf16(acc[mf][nf], aH[mf], bH[nf]);
                if (TERMS == 3) {
                    mma_bf16(acc[mf][nf], aH[mf], bL[nf]);
                    mma_bf16(acc[mf][nf], aL[mf], bH[nf]);
                }
            }
    }
}

__device__ __forceinline__ void epi_f32(
    float acc[2][8][4], const float* sbias, float* C,
    int rowBase, int wm, int wn, int lane, int M)
{
    #pragma unroll
    for (int mf = 0; mf < 2; mf++) {
        const int r0 = rowBase + wm * 32 + mf * 16 + (lane >> 2);
        #pragma unroll
        for (int nf = 0; nf < 8; nf++) {
            const int c  = wn * 64 + nf * 8 + (lane & 3) * 2;
            const float b0 = sbias[c], b1 = sbias[c + 1];
            if (r0 < M)
                *(float2*)(C + (long)r0 * DIM + c) =
                    make_float2(fmaxf(acc[mf][nf][0] + b0, 0.f),
                                fmaxf(acc[mf][nf][1] + b1, 0.f));
            if (r0 + 8 < M)
                *(float2*)(C + (long)(r0 + 8) * DIM + c) =
                    make_float2(fmaxf(acc[mf][nf][2] + b0, 0.f),
                                fmaxf(acc[mf][nf][3] + b1, 0.f));
        }
    }
}

__device__ __forceinline__ void epi_bf16(
    float acc[2][8][4], const float* sbias, __nv_bfloat16* C,
    int rowBase, int wm, int wn, int lane, int M)
{
    #pragma unroll
    for (int mf = 0; mf < 2; mf++) {
        const int r0 = rowBase + wm * 32 + mf * 16 + (lane >> 2);
        #pragma unroll
        for (int nf = 0; nf < 8; nf++) {
            const int c  = wn * 64 + nf * 8 + (lane & 3) * 2;
            const float b0 = sbias[c], b1 = sbias[c + 1];
            if (r0 < M)
                *(unsigned*)(C + (long)r0 * DIM + c) =
                    pack_bf2(fmaxf(acc[mf][nf][0] + b0, 0.f),
                             fmaxf(acc[mf][nf][1] + b1, 0.f));
            if (r0 + 8 < M)
                *(unsigned*)(C + (long)(r0 + 8) * DIM + c) =
                    pack_bf2(fmaxf(acc[mf][nf][2] + b0, 0.f),
                             fmaxf(acc[mf][nf][3] + b1, 0.f));
        }
    }
}

__device__ __forceinline__ void stage_w(
    char* sm, unsigned oWhi, unsigned oWlo, int wslot, int tid)
{
    const unsigned short* WH = g_W4[2 * wslot];
    const unsigned short* WL = g_W4[2 * wslot + 1];
    #pragma unroll
    for (int u = 0; u < 8; u++) {
        const int g  = u * 256 + tid;
        const int n  = g >> 4, kc = g & 15;
        const unsigned o = sw_off(n, kc);
        *(uint4*)(sm + oWhi + o) = *(const uint4*)(WH + n * DIM + kc * 8);
        *(uint4*)(sm + oWlo + o) = *(const uint4*)(WL + n * DIM + kc * 8);
    }
}

// ===========================================================================
// Fused node transforms (unchanged)
// ===========================================================================
#define NSM_AHI  0u
#define NSM_ALO  32768u
#define NSM_WHI  65536u
#define NSM_WLO  98304u
#define NSM_BIAS 131072u
#define NSMEM    133120

__global__ void __launch_bounds__(256)
node_all(const float* __restrict__ A, const int* __restrict__ gidx,
         const float* __restrict__ bq, const float* __restrict__ bq2,
         const float* __restrict__ bk, const float* __restrict__ bv,
         __nv_bfloat16* __restrict__ Qg, __nv_bfloat16* __restrict__ Q2,
         __nv_bfloat16* __restrict__ K0, float* __restrict__ V0)
{
    extern __shared__ char sm[];
    const unsigned sb = smem_u32(sm);
    const int tid  = threadIdx.x;
    const int wid  = tid >> 5;
    const int lane = tid & 31;
    const int wm   = wid & 3;
    const int wn   = wid >> 2;
    const int rowBase = blockIdx.x * 128;

    if (tid < 128) {
        ((float*)(sm + NSM_BIAS))[tid]        = bq[tid];
        ((float*)(sm + NSM_BIAS + 512))[tid]  = bq2[tid];
        ((float*)(sm + NSM_BIAS + 1024))[tid] = bk[tid];
        ((float*)(sm + NSM_BIAS + 1536))[tid] = bv[tid];
    }

    #pragma unroll
    for (int u = 0; u < 8; u++) {
        const int g  = u * 256 + tid;
        const int r  = g >> 4, kc = g & 15;
        const int src = gidx[rowBase + r];
        const float4 x0 = *(const float4*)(A + (long)src * DIM + kc * 8);
        const float4 x1 = *(const float4*)(A + (long)src * DIM + kc * 8 + 4);
        const float xs[8] = {x0.x, x0.y, x0.z, x0.w, x1.x, x1.y, x1.z, x1.w};
        uint4 H, L;
        split8(xs, H, L);
        const unsigned o = sw_off(r, kc);
        *(uint4*)(sm + NSM_AHI + o) = H;
        *(uint4*)(sm + NSM_ALO + o) = L;
    }
    stage_w(sm, NSM_WHI, NSM_WLO, 0, tid);   // gat_wq
    __syncthreads();

    float acc[2][8][4];

    mma_loop<1>(sb, NSM_AHI, NSM_ALO, NSM_WHI, NSM_WLO, wm, wn, lane, acc);
    __syncthreads();
    stage_w(sm, NSM_WHI, NSM_WLO, 4, tid);   // sem_wq
    epi_bf16(acc, (const float*)(sm + NSM_BIAS), Qg, rowBase, wm, wn, lane, BATCH);
    __syncthreads();

    mma_loop<1>(sb, NSM_AHI, NSM_ALO, NSM_WHI, NSM_WLO, wm, wn, lane, acc);
    __syncthreads();
    stage_w(sm, NSM_WHI, NSM_WLO, 5, tid);   // sem_wk
    epi_bf16(acc, (const float*)(sm + NSM_BIAS + 512), Q2, rowBase, wm, wn, lane, BATCH);
    __syncthreads();

    mma_loop<1>(sb, NSM_AHI, NSM_ALO, NSM_WHI, NSM_WLO, wm, wn, lane, acc);
    __syncthreads();
    stage_w(sm, NSM_WHI, NSM_WLO, 6, tid);   // sem_wv
    epi_bf16(acc, (const float*)(sm + NSM_BIAS + 1024), K0, rowBase, wm, wn, lane, BATCH);
    __syncthreads();

    mma_loop<3>(sb, NSM_AHI, NSM_ALO, NSM_WHI, NSM_WLO, wm, wn, lane, acc);
    epi_f32(acc, (const float*)(sm + NSM_BIAS + 1536), V0, rowBase, wm, wn, lane, BATCH);
}

// ===========================================================================
// Item GEMM (unchanged)
// ===========================================================================
#define ISM_A    0u
#define ISM_W    32768u
#define ISM_BIAS 65536u
#define ISMEM    66048

__global__ void __launch_bounds__(256)
gemm_item(const float* __restrict__ A,
          const unsigned short* __restrict__ W0, const unsigned short* __restrict__ W1,
          const float* __restrict__ b0, const float* __restrict__ b1,
          __nv_bfloat16* __restrict__ KV, int M)
{
    const int y = blockIdx.y;
    const unsigned short* Wt = y ? W1 : W0;
    const float* bias = y ? b1 : b0;
    __nv_bfloat16* Cb = KV + (y ? 128 : 0);

    extern __shared__ char sm[];
    const unsigned sb = smem_u32(sm);
    const int tid  = threadIdx.x;
    const int wid  = tid >> 5;
    const int lane = tid & 31;
    const int wm   = wid & 3;
    const int wn   = wid >> 2;
    const int rowBase = blockIdx.x * 128;

    if (tid < 128) ((float*)(sm + ISM_BIAS))[tid] = bias[tid];

    #pragma unroll
    for (int u = 0; u < 8; u++) {
        const int g  = u * 256 + tid;
        const int r  = g >> 4, kc = g & 15;
        int R = rowBase + r; if (R >= M) R = M - 1;
        const float4 x0 = *(const float4*)(A + (long)R * DIM + kc * 8);
        const float4 x1 = *(const float4*)(A + (long)R * DIM + kc * 8 + 4);
        const float xs[8] = {x0.x, x0.y, x0.z, x0.w, x1.x, x1.y, x1.z, x1.w};
        *(uint4*)(sm + ISM_A + sw_off(r, kc)) = pack8f16(xs);
    }
    #pragma unroll
    for (int u = 0; u < 8; u++) {
        const int g  = u * 256 + tid;
        const int n  = g >> 4, kc = g & 15;
        *(uint4*)(sm + ISM_W + sw_off(n, kc)) = *(const uint4*)(Wt + n * DIM + kc * 8);
    }
    __syncthreads();

    float acc[2][8][4];
    #pragma unroll
    for (int i = 0; i < 2; i++)
        #pragma unroll
        for (int j = 0; j < 8; j++)
            #pragma unroll
            for (int q = 0; q < 4; q++) acc[i][j][q] = 0.f;

    #pragma unroll
    for (int ks = 0; ks < 8; ks++) {
        unsigned aH[2][4], bH[8][2];
        {
            const int r  = wm * 32 + (lane & 15);
            const int kc = ks * 2 + (lane >> 4);
            ldm4(aH[0][0], aH[0][1], aH[0][2], aH[0][3], sb + ISM_A + sw_off(r,      kc));
            ldm4(aH[1][0], aH[1][1], aH[1][2], aH[1][3], sb + ISM_A + sw_off(r + 16, kc));
        }
        {
            const int grp  = lane >> 3;
            const int nloc = (lane & 7) + ((grp >> 1) << 3);
            const int kc   = ks * 2 + (grp & 1);
            #pragma unroll
            for (int j = 0; j < 4; j++) {
                const int n = wn * 64 + j * 16 + nloc;
                ldm4(bH[2*j][0], bH[2*j][1], bH[2*j+1][0], bH[2*j+1][1],
                     sb + ISM_W + sw_off(n, kc));
            }
        }
        #pragma unroll
        for (int mf = 0; mf < 2; mf++)
            #pragma unroll
            for (int nf = 0; nf < 8; nf++)
                mma_f16(acc[mf][nf], aH[mf], bH[nf]);
    }

    const float* sbias = (const float*)(sm + ISM_BIAS);
    #pragma unroll
    for (int mf = 0; mf < 2; mf++) {
        const int r0 = rowBase + wm * 32 + mf * 16 + (lane >> 2);
        #pragma unroll
        for (int nf = 0; nf < 8; nf++) {
            const int c  = wn * 64 + nf * 8 + (lane & 3) * 2;
            const float b0v = sbias[c], b1v = sbias[c + 1];
            if (r0 < M) {
                const unsigned v = pack_bf2(fmaxf(acc[mf][nf][0] + b0v, 0.f),
                                            fmaxf(acc[mf][nf][1] + b1v, 0.f));
                *(unsigned*)(Cb + (long)r0 * 256 + c) = v;
            }
            if (r0 + 8 < M) {
                const unsigned v = pack_bf2(fmaxf(acc[mf][nf][2] + b0v, 0.f),
                                            fmaxf(acc[mf][nf][3] + b1v, 0.f));
                *(unsigned*)(Cb + (long)(r0 + 8) * 256 + c) = v;
            }
        }
    }
}

// ===========================================================================
// Fused tail (unchanged from R13)
// ===========================================================================
#define TSM_AHI  0u
#define TSM_ALO  32768u
#define TSM_W1H  65536u
#define TSM_W1L  98304u
#define TSM_W2H  131072u
#define TSM_W2L  163840u
#define TSM_BIAS 196608u
#define TSM_P1   198656u
#define TSMEM    199168

__global__ void __launch_bounds__(256)
tail_fused(const float* __restrict__ Y,
           const __nv_bfloat16* __restrict__ Q2, const __nv_bfloat16* __restrict__ K0,
           const float* __restrict__ V0,
           const float* __restrict__ bo, const float* __restrict__ bk,
           const float* __restrict__ bv, const float* __restrict__ bo2,
           float* __restrict__ out)
{
    extern __shared__ char sm[];
    const unsigned sb = smem_u32(sm);
    const int tid  = threadIdx.x;
    const int wid  = tid >> 5;
    const int lane = tid & 31;
    const int wm   = wid & 3;
    const int wn   = wid >> 2;
    const int rowBase = blockIdx.x * 128;

    if (tid < 128) {
        ((float*)(sm + TSM_BIAS))[tid]        = bo[tid];
        ((float*)(sm + TSM_BIAS + 512))[tid]  = bk[tid];
        ((float*)(sm + TSM_BIAS + 1024))[tid] = bv[tid];
        ((float*)(sm + TSM_BIAS + 1536))[tid] = bo2[tid];
    }

    #pragma unroll
    for (int u = 0; u < 8; u++) {
        const int g  = u * 256 + tid;
        const int r  = g >> 4, kc = g & 15;
        const int R = rowBase + r;
        const float4 x0 = *(const float4*)(Y + (long)R * DIM + kc * 8);
        const float4 x1 = *(const float4*)(Y + (long)R * DIM + kc * 8 + 4);
        const float xs[8] = {x0.x, x0.y, x0.z, x0.w, x1.x, x1.y, x1.z, x1.w};
        uint4 H, L;
        split8(xs, H, L);
        const unsigned o = sw_off(r, kc);
        *(uint4*)(sm + TSM_AHI + o) = H;
        *(uint4*)(sm + TSM_ALO + o) = L;
    }
    stage_w(sm, TSM_W1H, TSM_W1L, 3, tid);   // gat_wo
    stage_w(sm, TSM_W2H, TSM_W2L, 5, tid);   // sem_wk
    __syncthreads();

    float acc[2][8][4];

    // phase 1: Agg
    mma_loop<3>(sb, TSM_AHI, TSM_ALO, TSM_W1H, TSM_W1L, wm, wn, lane, acc);
    __syncthreads();
    {
        const float* sbo = (const float*)(sm + TSM_BIAS);
        #pragma unroll
        for (int mf = 0; mf < 2; mf++) {
            const int r = wm * 32 + mf * 16 + (lane >> 2);
            #pragma unroll
            for (int nf = 0; nf < 8; nf++) {
                const int c  = wn * 64 + nf * 8 + (lane & 3) * 2;
                const float b0 = sbo[c], b1 = sbo[c + 1];
                store_pair_split(sm, TSM_AHI, TSM_ALO, r, c,
                                 fmaxf(acc[mf][nf][0] + b0, 0.f),
                                 fmaxf(acc[mf][nf][1] + b1, 0.f));
                store_pair_split(sm, TSM_AHI, TSM_ALO, r + 8, c,
                                 fmaxf(acc[mf][nf][2] + b0, 0.f),
                                 fmaxf(acc[mf][nf][3] + b1, 0.f));
            }
        }
    }
    stage_w(sm, TSM_W1H, TSM_W1L, 6, tid);   // sem_wv
    __syncthreads();

    // phase 2: K1 -> stash bf16 into W2H
    mma_loop<1>(sb, TSM_AHI, TSM_ALO, TSM_W2H, TSM_W2L, wm, wn, lane, acc);
    __syncthreads();
    {
        const float* sbk = (const float*)(sm + TSM_BIAS + 512);
        #pragma unroll
        for (int mf = 0; mf < 2; mf++) {
            const int r = wm * 32 + mf * 16 + (lane >> 2);
            #pragma unroll
            for (int nf = 0; nf < 8; nf++) {
                const int c  = wn * 64 + nf * 8 + (lane & 3) * 2;
                const float b0 = sbk[c], b1 = sbk[c + 1];
                *(unsigned*)(sm + TSM_W2H + r * 256 + c * 2) =
                    pack_bf2(fmaxf(acc[mf][nf][0] + b0, 0.f),
                             fmaxf(acc[mf][nf][1] + b1, 0.f));
                *(unsigned*)(sm + TSM_W2H + (r + 8) * 256 + c * 2) =
                    pack_bf2(fmaxf(acc[mf][nf][2] + b0, 0.f),
                             fmaxf(acc[mf][nf][3] + b1, 0.f));
            }
        }
    }
    __syncthreads();

    // phase 3: V1 (registers)
    mma_loop<3>(sb, TSM_AHI, TSM_ALO, TSM_W1H, TSM_W1L, wm, wn, lane, acc);

    // phase 4: per-row 2-key softmax
    {
        const float scale = 0.08838834764831845f;
        #pragma unroll
        for (int u = 0; u < 8; u++) {
            const int g  = u * 256 + tid;
            const int r  = g >> 4, cl = g & 15;
            const long base = (long)(rowBase + r) * DIM + cl * 8;

            const uint4 qu  = *(const uint4*)(Q2 + base);
            const uint4 k0u = *(const uint4*)(K0 + base);
            const uint4 k1u = *(const uint4*)(sm + TSM_W2H + r * 256 + cl * 16);

            float s0, s1;
            s0  = bflo(qu.x)*bflo(k0u.x) + bfhi(qu.x)*bfhi(k0u.x);
            s0 += bflo(qu.y)*bflo(k0u.y) + bfhi(qu.y)*bfhi(k0u.y);
            s0 += bflo(qu.z)*bflo(k0u.z) + bfhi(qu.z)*bfhi(k0u.z);
            s0 += bflo(qu.w)*bflo(k0u.w) + bfhi(qu.w)*bfhi(k0u.w);
            s1  = bflo(qu.x)*bflo(k1u.x) + bfhi(qu.x)*bfhi(k1u.x);
            s1 += bflo(qu.y)*bflo(k1u.y) + bfhi(qu.y)*bfhi(k1u.y);
            s1 += bflo(qu.z)*bflo(k1u.z) + bfhi(qu.z)*bfhi(k1u.z);
            s1 += bflo(qu.w)*bflo(k1u.w) + bfhi(qu.w)*bfhi(k1u.w);

            #pragma unroll
            for (int o = 8; o; o >>= 1) {
                s0 += __shfl_xor_sync(0xffffffffu, s0, o);
                s1 += __shfl_xor_sync(0xffffffffu, s1, o);
            }
            if (cl == 0) {
                s0 *= scale; s1 *= scale;
                const float m  = fmaxf(s0, s1);
                const float e0 = __expf(s0 - m);
                const float e1 = __expf(s1 - m);
                ((float*)(sm + TSM_P1))[r] = e1 / (e0 + e1);
            }
        }
    }
    __syncthreads();

    // phase 5: Y2 -> A slots; stage wo2
    {
        const float* sbv = (const float*)(sm + TSM_BIAS + 1024);
        const float* p1s = (const float*)(sm + TSM_P1);
        #pragma unroll
        for (int mf = 0; mf < 2; mf++) {
            const int r = wm * 32 + mf * 16 + (lane >> 2);
            #pragma unroll
            for (int nf = 0; nf < 8; nf++) {
                const int c  = wn * 64 + nf * 8 + (lane & 3) * 2;
                const float b0 = sbv[c], b1 = sbv[c + 1];
                {
                    const float p1 = p1s[r], p0 = 1.f - p1;
                    const float2 v0 = *(const float2*)(V0 + (long)(rowBase + r) * DIM + c);
                    const float v1a = fmaxf(acc[mf][nf][0] + b0, 0.f);
                    const float v1b = fmaxf(acc[mf][nf][1] + b1, 0.f);
                    store_pair_split(sm, TSM_AHI, TSM_ALO, r, c,
                                     p0 * v0.x + p1 * v1a, p0 * v0.y + p1 * v1b);
                }
                {
                    const float p1 = p1s[r + 8], p0 = 1.f - p1;
                    const float2 v0 = *(const float2*)(V0 + (long)(rowBase + r + 8) * DIM + c);
                    const float v1a = fmaxf(acc[mf][nf][2] + b0, 0.f);
                    const float v1b = fmaxf(acc[mf][nf][3] + b1, 0.f);
                    store_pair_split(sm, TSM_AHI, TSM_ALO, r + 8, c,
                                     p0 * v0.x + p1 * v1a, p0 * v0.y + p1 * v1b);
                }
            }
        }
    }
    stage_w(sm, TSM_W2H, TSM_W2L, 7, tid);   // sem_wo
    __syncthreads();

    // phase 6: out
    mma_loop<3>(sb, TSM_AHI, TSM_ALO, TSM_W2H, TSM_W2L, wm, wn, lane, acc);
    epi_f32(acc, (const float*)(sm + TSM_BIAS + 1536), out, rowBase, wm, wn, lane, BATCH);
}

// ---------------------------------------------------------------------------
// GAT attention v4b (unchanged)
// ---------------------------------------------------------------------------
__global__ void __launch_bounds__(256)
gat_attn(const __nv_bfloat16* __restrict__ Q, const int* __restrict__ movies,
         const __nv_bfloat16* __restrict__ KV, float* __restrict__ Y)
{
    const int w    = threadIdx.x >> 5;
    const int lane = threadIdx.x & 31;
    const int half = lane >> 4;
    const int cl   = lane & 15;
    const int b    = blockIdx.x * 8 + w;

    __shared__ int sidx[8][NHIST];

    if (lane < NHIST)      sidx[w][lane]      = movies[(b * NHIST + lane) * 2];
    if (lane + 32 < NHIST) sidx[w][lane + 32] = movies[(b * NHIST + lane + 32) * 2];
    __syncwarp();

    const float scale = 0.08838834764831845f;
    const uint4 qu = *(const uint4*)(Q + (long)b * DIM + cl * 8);
    float4 qa, qb;
    qa.x = bflo(qu.x) * scale; qa.y = bfhi(qu.x) * scale;
    qa.z = bflo(qu.y) * scale; qa.w = bfhi(qu.y) * scale;
    qb.x = bflo(qu.z) * scale; qb.y = bfhi(qu.z) * scale;
    qb.z = bflo(qu.w) * scale; qb.w = bfhi(qu.w) * scale;

    float num[8];
    #pragma unroll
    for (int i = 0; i < 8; i++) num[i] = 0.f;
    float den = 0.f;

    #pragma unroll
    for (int t0 = 0; t0 < 25; t0 += 5) {
        uint4 kr[5];
        #pragma unroll
        for (int j = 0; j < 5; j++)
            kr[j] = *(const uint4*)(KV + (long)sidx[w][2*(t0+j) + half] * 256 + cl * 8);

        float sc[5];
        #pragma unroll
        for (int j = 0; j < 5; j++) {
            float s;
            s  = qa.x * bflo(kr[j].x) + qa.y * bfhi(kr[j].x);
            s += qa.z * bflo(kr[j].y) + qa.w * bfhi(kr[j].y);
            s += qb.x * bflo(kr[j].z) + qb.y * bfhi(kr[j].z);
            s += qb.z * bflo(kr[j].w) + qb.w * bfhi(kr[j].w);
            sc[j] = s;
        }

        uint4 vr[5];
        #pragma unroll
        for (int j = 0; j < 5; j++)
            vr[j] = *(const uint4*)(KV + (long)sidx[w][2*(t0+j) + half] * 256 + 128 + cl * 8);

        #pragma unroll
        for (int j = 0; j < 5; j++)
            #pragma unroll
            for (int off = 8; off; off >>= 1)
                sc[j] += __shfl_xor_sync(0xffffffffu, sc[j], off);

        #pragma unroll
        for (int j = 0; j < 5; j++) {
            const float e = __expf(sc[j]);
            den += e;
            num[0] = fmaf(e, bflo(vr[j].x), num[0]);
            num[1] = fmaf(e, bfhi(vr[j].x), num[1]);
            num[2] = fmaf(e, bflo(vr[j].y), num[2]);
            num[3] = fmaf(e, bfhi(vr[j].y), num[3]);
            num[4] = fmaf(e, bflo(vr[j].z), num[4]);
            num[5] = fmaf(e, bfhi(vr[j].z), num[5]);
            num[6] = fmaf(e, bflo(vr[j].w), num[6]);
            num[7] = fmaf(e, bfhi(vr[j].w), num[7]);
        }
    }

    #pragma unroll
    for (int i = 0; i < 8; i++)
        num[i] += __shfl_xor_sync(0xffffffffu, num[i], 16);
    den += __shfl_xor_sync(0xffffffffu, den, 16);

    if (half == 0) {
        const float inv = 1.0f / den;
        *(float4*)(Y + (long)b * DIM + cl * 8) =
            make_float4(num[0]*inv, num[1]*inv, num[2]*inv, num[3]*inv);
        *(float4*)(Y + (long)b * DIM + cl * 8 + 4) =
            make_float4(num[4]*inv, num[5]*inv, num[6]*inv, num[7]*inv);
    }
}

// ---------------------------------------------------------------------------
// Host launcher: w_setup -> (node_all || gemm_item via stream fork) ->
//                gat_attn -> tail_fused
// ---------------------------------------------------------------------------
extern "C" void kernel_launch(void* const* d_in, const int* in_sizes, int n_in,
                              void* d_out, int out_size)
{
    const int*   uids       = (const int*)  d_in[0];
    const int*   u_movies   = (const int*)  d_in[2];
    const float* user_table = (const float*)d_in[3];
    const float* item_table = (const float*)d_in[5];
    const float* gat_wq = (const float*)d_in[6],  *gat_bq = (const float*)d_in[7];
    const float* gat_wk = (const float*)d_in[8],  *gat_bk = (const float*)d_in[9];
    const float* gat_wv = (const float*)d_in[10], *gat_bv = (const float*)d_in[11];
    const float* gat_wo = (const float*)d_in[12], *gat_bo = (const float*)d_in[13];
    const float* sem_wq = (const float*)d_in[14], *sem_bq = (const float*)d_in[15];
    const float* sem_wk = (const float*)d_in[16], *sem_bk = (const float*)d_in[17];
    const float* sem_wv = (const float*)d_in[18], *sem_bv = (const float*)d_in[19];
    const float* sem_wo = (const float*)d_in[20], *sem_bo = (const float*)d_in[21];
    float* out = (float*)d_out;

    __nv_bfloat16 *KV, *Qg, *Q2, *K0;
    unsigned short *Wh0, *Wh1;
    float *V0, *Y;
    cudaGetSymbolAddress((void**)&KV,  g_KV);
    cudaGetSymbolAddress((void**)&Qg,  g_Qg);
    cudaGetSymbolAddress((void**)&Q2,  g_Q2);
    cudaGetSymbolAddress((void**)&K0,  g_K0);
    cudaGetSymbolAddress((void**)&V0,  g_V0);
    cudaGetSymbolAddress((void**)&Y,   g_Y);
    {
        void* p;
        cudaGetSymbolAddress(&p, g_Wh);
        Wh0 = (unsigned short*)p;
        Wh1 = Wh0 + DIM * DIM;
    }

    // One-time setup on the first (non-captured) correctness call:
    // func attrs + a side stream and fork/join events for the captured graph.
    static cudaStream_t s_item = nullptr;
    static cudaEvent_t  evFork = nullptr, evJoin = nullptr;
    if (!s_item) {
        cudaFuncSetAttribute(node_all,   cudaFuncAttributeMaxDynamicSharedMemorySize, NSMEM);
        cudaFuncSetAttribute(gemm_item,  cudaFuncAttributeMaxDynamicSharedMemorySize, ISMEM);
        cudaFuncSetAttribute(tail_fused, cudaFuncAttributeMaxDynamicSharedMemorySize, TSMEM);
        cudaStreamCreateWithFlags(&s_item, cudaStreamNonBlocking);
        cudaEventCreateWithFlags(&evFork, cudaEventDisableTiming);
        cudaEventCreateWithFlags(&evJoin, cudaEventDisableTiming);
    }

    const dim3 blk(256);
    const int gItems = (NITEMS + 127) / 128;     // 782
    const int gBatch = BATCH / 128;              // 128

    // 0: weight transpose + splits (producer for both branches)
    w_setup<<<64, 256>>>(gat_wq, gat_wk, gat_wv, gat_wo,
                         sem_wq, sem_wk, sem_wv, sem_wo);

    // fork: gemm_item runs on the side stream, concurrent with node_all
    cudaEventRecord(evFork, 0);
    cudaStreamWaitEvent(s_item, evFork, 0);

    gemm_item<<<dim3(gItems, 2), blk, ISMEM, s_item>>>(item_table, Wh0, Wh1,
                                                       gat_bk, gat_bv, KV, NITEMS);

    node_all<<<gBatch, blk, NSMEM>>>(user_table, uids,
                                     gat_bq, sem_bq, sem_bk, sem_bv,
                                     Qg, Q2, K0, V0);

    // join: gat_attn needs both Qg (default stream) and KV (side stream)
    cudaEventRecord(evJoin, s_item);
    cudaStreamWaitEvent(0, evJoin, 0);

    // 3: GAT attention
    gat_attn<<<BATCH / 8, blk>>>(Qg, u_movies, KV, Y);

    // 4: fused tail
    tail_fused<<<gBatch, blk, TSMEM>>>(Y, Q2, K0, V0,
                                       gat_bo, sem_bk, sem_bv, sem_bo, out);
}

// round 15
// speedup vs baseline: 1.0269x; 1.0269x over previous
#include <cuda_runtime.h>
#include <cuda_bf16.h>
#include <cuda_fp16.h>
#include <math.h>

// ---------------------------------------------------------------------------
// Problem constants
// ---------------------------------------------------------------------------
#define BATCH   16384
#define NHIST   50
#define DIM     128
#define NITEMS  100000

// ---------------------------------------------------------------------------
// Scratch (static device globals)
// ---------------------------------------------------------------------------
__device__ __nv_bfloat16 g_KV[NITEMS * 256];   // per item: 128 bf16 K | 128 bf16 V
__device__ __nv_bfloat16 g_Qg [BATCH * DIM];
__device__ __nv_bfloat16 g_Q2 [BATCH * DIM];
__device__ __nv_bfloat16 g_K0 [BATCH * DIM];
__device__ float g_V0 [BATCH * DIM];
__device__ float g_Y  [BATCH * DIM];
// bf16 weight splits, transposed to [n][k]: slot 2*w = hi, 2*w+1 = lo
// w: 0=gat_wq 1=gat_wk 2=gat_wv 3=gat_wo 4=sem_wq 5=sem_wk 6=sem_wv 7=sem_wo
__device__ unsigned short g_W4[16][DIM * DIM];
// fp16 transposed weights for the item GEMM: 0=gat_wk, 1=gat_wv
__device__ unsigned short g_Wh[2][DIM * DIM];

// ---------------------------------------------------------------------------
// helpers
// ---------------------------------------------------------------------------
__device__ __forceinline__ unsigned smem_u32(const void* p) {
    unsigned a;
    asm("{ .reg .u64 t; cvta.to.shared.u64 t, %1; cvt.u32.u64 %0, t; }"
        : "=r"(a) : "l"(p));
    return a;
}
__device__ __forceinline__ void ldm4(unsigned& r0, unsigned& r1,
                                     unsigned& r2, unsigned& r3, unsigned addr) {
    asm volatile("ldmatrix.sync.aligned.m8n8.x4.shared.b16 {%0,%1,%2,%3}, [%4];"
                 : "=r"(r0), "=r"(r1), "=r"(r2), "=r"(r3) : "r"(addr));
}
__device__ __forceinline__ void mma_bf16(float* d, const unsigned* a, const unsigned* b) {
    asm volatile("mma.sync.aligned.m16n8k16.row.col.f32.bf16.bf16.f32 "
                 "{%0,%1,%2,%3}, {%4,%5,%6,%7}, {%8,%9}, {%0,%1,%2,%3};"
                 : "+f"(d[0]), "+f"(d[1]), "+f"(d[2]), "+f"(d[3])
                 : "r"(a[0]), "r"(a[1]), "r"(a[2]), "r"(a[3]),
                   "r"(b[0]), "r"(b[1]));
}
__device__ __forceinline__ void mma_f16(float* d, const unsigned* a, const unsigned* b) {
    asm volatile("mma.sync.aligned.m16n8k16.row.col.f32.f16.f16.f32 "
                 "{%0,%1,%2,%3}, {%4,%5,%6,%7}, {%8,%9}, {%0,%1,%2,%3};"
                 : "+f"(d[0]), "+f"(d[1]), "+f"(d[2]), "+f"(d[3])
                 : "r"(a[0]), "r"(a[1]), "r"(a[2]), "r"(a[3]),
                   "r"(b[0]), "r"(b[1]));
}
// smem byte offset for (row, 8-elem 16B chunk kc): 256B rows, XOR swizzle
__device__ __forceinline__ unsigned sw_off(int row, int kc) {
    return (unsigned)(row * 256 + ((kc ^ (row & 7)) << 4));
}
// split 8 fp32 -> two uint4 of bf16 (hi, lo = residual)
__device__ __forceinline__ void split8(const float* xs, uint4& H, uint4& L) {
    unsigned hw[4], lw[4];
    #pragma unroll
    for (int j = 0; j < 4; j++) {
        __nv_bfloat16 h0 = __float2bfloat16(xs[2*j]);
        __nv_bfloat16 h1 = __float2bfloat16(xs[2*j+1]);
        __nv_bfloat16 l0 = __float2bfloat16(xs[2*j]   - __bfloat162float(h0));
        __nv_bfloat16 l1 = __float2bfloat16(xs[2*j+1] - __bfloat162float(h1));
        hw[j] = (unsigned)*(unsigned short*)&h0 | ((unsigned)*(unsigned short*)&h1 << 16);
        lw[j] = (unsigned)*(unsigned short*)&l0 | ((unsigned)*(unsigned short*)&l1 << 16);
    }
    H = make_uint4(hw[0], hw[1], hw[2], hw[3]);
    L = make_uint4(lw[0], lw[1], lw[2], lw[3]);
}
// 8 fp32 -> uint4 of fp16
__device__ __forceinline__ uint4 pack8f16(const float* xs) {
    unsigned hw[4];
    #pragma unroll
    for (int j = 0; j < 4; j++) {
        const unsigned short a = __half_as_ushort(__float2half_rn(xs[2*j]));
        const unsigned short b = __half_as_ushort(__float2half_rn(xs[2*j+1]));
        hw[j] = (unsigned)a | ((unsigned)b << 16);
    }
    return make_uint4(hw[0], hw[1], hw[2], hw[3]);
}
__device__ __forceinline__ unsigned pack_bf2(float a, float b) {
    __nv_bfloat16 x = __float2bfloat16(a), y = __float2bfloat16(b);
    return (unsigned)*(unsigned short*)&x | ((unsigned)*(unsigned short*)&y << 16);
}
// bf16x2 unpack via shift/mask
__device__ __forceinline__ float bflo(unsigned u) { return __uint_as_float(u << 16); }
__device__ __forceinline__ float bfhi(unsigned u) { return __uint_as_float(u & 0xffff0000u); }
// write a (v0,v1) pair as bf16 hi + residual lo into split A slots
__device__ __forceinline__ void store_pair_split(
    char* sm, unsigned oHi, unsigned oLo, int r, int c, float v0, float v1)
{
    const unsigned off = sw_off(r, c >> 3) + (c & 7) * 2;
    *(unsigned*)(sm + oHi + off) = pack_bf2(v0, v1);
    *(unsigned*)(sm + oLo + off) =
        pack_bf2(v0 - bfhi(pack_bf2(0.f, v0)), v1 - bfhi(pack_bf2(0.f, v1)));
}

// ===========================================================================
// Setup: transpose + split all weight matrices
// ===========================================================================
__global__ void w_setup(const float* w0, const float* w1, const float* w2,
                        const float* w3, const float* w4, const float* w5,
                        const float* w6, const float* w7)
{
    const int i = blockIdx.x * blockDim.x + threadIdx.x;
    if (i >= DIM * DIM) return;
    const float* ws[8] = {w0, w1, w2, w3, w4, w5, w6, w7};
    const int k = i >> 7, n = i & 127;
    const int dst = n * DIM + k;
    #pragma unroll
    for (int w = 0; w < 8; w++) {
        const float a = ws[w][i];
        __nv_bfloat16 h = __float2bfloat16(a);
        __nv_bfloat16 l = __float2bfloat16(a - __bfloat162float(h));
        g_W4[2*w    ][dst] = *(unsigned short*)&h;
        g_W4[2*w + 1][dst] = *(unsigned short*)&l;
    }
    g_Wh[0][dst] = __half_as_ushort(__float2half_rn(w1[i]));   // gat_wk
    g_Wh[1][dst] = __half_as_ushort(__float2half_rn(w2[i]));   // gat_wv
}

// ===========================================================================
// Shared GEMM building blocks. 8 warps (4x2), warp tile 32x64, CTA 128x128.
// ===========================================================================
template<int TERMS>
__device__ __forceinline__ void mma_loop(
    unsigned sb, unsigned oAhi, unsigned oAlo, unsigned oWhi, unsigned oWlo,
    int wm, int wn, int lane, float acc[2][8][4])
{
    #pragma unroll
    for (int i = 0; i < 2; i++)
        #pragma unroll
        for (int j = 0; j < 8; j++)
            #pragma unroll
            for (int q = 0; q < 4; q++) acc[i][j][q] = 0.f;

    #pragma unroll
    for (int ks = 0; ks < 8; ks++) {
        unsigned aH[2][4], aL[2][4], bH[8][2], bL[8][2];
        {
            const int r  = wm * 32 + (lane & 15);
            const int kc = ks * 2 + (lane >> 4);
            ldm4(aH[0][0], aH[0][1], aH[0][2], aH[0][3], sb + oAhi + sw_off(r,      kc));
            ldm4(aH[1][0], aH[1][1], aH[1][2], aH[1][3], sb + oAhi + sw_off(r + 16, kc));
            if (TERMS == 3) {
                ldm4(aL[0][0], aL[0][1], aL[0][2], aL[0][3], sb + oAlo + sw_off(r,      kc));
                ldm4(aL[1][0], aL[1][1], aL[1][2], aL[1][3], sb + oAlo + sw_off(r + 16, kc));
            }
        }
        {
            const int grp  = lane >> 3;
            const int nloc = (lane & 7) + ((grp >> 1) << 3);
            const int kc   = ks * 2 + (grp & 1);
            #pragma unroll
            for (int j = 0; j < 4; j++) {
                const int n = wn * 64 + j * 16 + nloc;
                ldm4(bH[2*j][0], bH[2*j][1], bH[2*j+1][0], bH[2*j+1][1],
                     sb + oWhi + sw_off(n, kc));
                if (TERMS == 3)
                    ldm4(bL[2*j][0], bL[2*j][1], bL[2*j+1][0], bL[2*j+1][1],
                         sb + oWlo + sw_off(n, kc));
            }
        }
        #pragma unroll
        for (int mf = 0; mf < 2; mf++)
            #pragma unroll
            for (int nf = 0; nf < 8; nf++) {
                mma_bf16(acc[mf][nf], aH[mf], bH[nf]);
                if (TERMS == 3) {
                    mma_bf16(acc[mf][nf], aH[mf], bL[nf]);
                    mma_bf16(acc[mf][nf], aL[mf], bH[nf]);
                }
            }
    }
}

__device__ __forceinline__ void epi_f32(
    float acc[2][8][4], const float* sbias, float* C,
    int rowBase, int wm, int wn, int lane, int M)
{
    #pragma unroll
    for (int mf = 0; mf < 2; mf++) {
        const int r0 = rowBase + wm * 32 + mf * 16 + (lane >> 2);
        #pragma unroll
        for (int nf = 0; nf < 8; nf++) {
            const int c  = wn * 64 + nf * 8 + (lane & 3) * 2;
            const float b0 = sbias[c], b1 = sbias[c + 1];
            if (r0 < M)
                *(float2*)(C + (long)r0 * DIM + c) =
                    make_float2(fmaxf(acc[mf][nf][0] + b0, 0.f),
                                fmaxf(acc[mf][nf][1] + b1, 0.f));
            if (r0 + 8 < M)
                *(float2*)(C + (long)(r0 + 8) * DIM + c) =
                    make_float2(fmaxf(acc[mf][nf][2] + b0, 0.f),
                                fmaxf(acc[mf][nf][3] + b1, 0.f));
        }
    }
}

__device__ __forceinline__ void epi_bf16(
    float acc[2][8][4], const float* sbias, __nv_bfloat16* C,
    int rowBase, int wm, int wn, int lane, int M)
{
    #pragma unroll
    for (int mf = 0; mf < 2; mf++) {
        const int r0 = rowBase + wm * 32 + mf * 16 + (lane >> 2);
        #pragma unroll
        for (int nf = 0; nf < 8; nf++) {
            const int c  = wn * 64 + nf * 8 + (lane & 3) * 2;
            const float b0 = sbias[c], b1 = sbias[c + 1];
            if (r0 < M)
                *(unsigned*)(C + (long)r0 * DIM + c) =
                    pack_bf2(fmaxf(acc[mf][nf][0] + b0, 0.f),
                             fmaxf(acc[mf][nf][1] + b1, 0.f));
            if (r0 + 8 < M)
                *(unsigned*)(C + (long)(r0 + 8) * DIM + c) =
                    pack_bf2(fmaxf(acc[mf][nf][2] + b0, 0.f),
                             fmaxf(acc[mf][nf][3] + b1, 0.f));
        }
    }
}

__device__ __forceinline__ void stage_w(
    char* sm, unsigned oWhi, unsigned oWlo, int wslot, int tid)
{
    const unsigned short* WH = g_W4[2 * wslot];
    const unsigned short* WL = g_W4[2 * wslot + 1];
    #pragma unroll
    for (int u = 0; u < 8; u++) {
        const int g  = u * 256 + tid;
        const int n  = g >> 4, kc = g & 15;
        const unsigned o = sw_off(n, kc);
        *(uint4*)(sm + oWhi + o) = *(const uint4*)(WH + n * DIM + kc * 8);
        *(uint4*)(sm + oWlo + o) = *(const uint4*)(WL + n * DIM + kc * 8);
    }
}

// ===========================================================================
// Fused node transforms (unchanged)
// ===========================================================================
#define NSM_AHI  0u
#define NSM_ALO  32768u
#define NSM_WHI  65536u
#define NSM_WLO  98304u
#define NSM_BIAS 131072u
#define NSMEM    133120

__global__ void __launch_bounds__(256)
node_all(const float* __restrict__ A, const int* __restrict__ gidx,
         const float* __restrict__ bq, const float* __restrict__ bq2,
         const float* __restrict__ bk, const float* __restrict__ bv,
         __nv_bfloat16* __restrict__ Qg, __nv_bfloat16* __restrict__ Q2,
         __nv_bfloat16* __restrict__ K0, float* __restrict__ V0)
{
    extern __shared__ char sm[];
    const unsigned sb = smem_u32(sm);
    const int tid  = threadIdx.x;
    const int wid  = tid >> 5;
    const int lane = tid & 31;
    const int wm   = wid & 3;
    const int wn   = wid >> 2;
    const int rowBase = blockIdx.x * 128;

    if (tid < 128) {
        ((float*)(sm + NSM_BIAS))[tid]        = bq[tid];
        ((float*)(sm + NSM_BIAS + 512))[tid]  = bq2[tid];
        ((float*)(sm + NSM_BIAS + 1024))[tid] = bk[tid];
        ((float*)(sm + NSM_BIAS + 1536))[tid] = bv[tid];
    }

    #pragma unroll
    for (int u = 0; u < 8; u++) {
        const int g  = u * 256 + tid;
        const int r  = g >> 4, kc = g & 15;
        const int src = gidx[rowBase + r];
        const float4 x0 = *(const float4*)(A + (long)src * DIM + kc * 8);
        const float4 x1 = *(const float4*)(A + (long)src * DIM + kc * 8 + 4);
        const float xs[8] = {x0.x, x0.y, x0.z, x0.w, x1.x, x1.y, x1.z, x1.w};
        uint4 H, L;
        split8(xs, H, L);
        const unsigned o = sw_off(r, kc);
        *(uint4*)(sm + NSM_AHI + o) = H;
        *(uint4*)(sm + NSM_ALO + o) = L;
    }
    stage_w(sm, NSM_WHI, NSM_WLO, 0, tid);   // gat_wq
    __syncthreads();

    float acc[2][8][4];

    mma_loop<1>(sb, NSM_AHI, NSM_ALO, NSM_WHI, NSM_WLO, wm, wn, lane, acc);
    __syncthreads();
    stage_w(sm, NSM_WHI, NSM_WLO, 4, tid);   // sem_wq
    epi_bf16(acc, (const float*)(sm + NSM_BIAS), Qg, rowBase, wm, wn, lane, BATCH);
    __syncthreads();

    mma_loop<1>(sb, NSM_AHI, NSM_ALO, NSM_WHI, NSM_WLO, wm, wn, lane, acc);
    __syncthreads();
    stage_w(sm, NSM_WHI, NSM_WLO, 5, tid);   // sem_wk
    epi_bf16(acc, (const float*)(sm + NSM_BIAS + 512), Q2, rowBase, wm, wn, lane, BATCH);
    __syncthreads();

    mma_loop<1>(sb, NSM_AHI, NSM_ALO, NSM_WHI, NSM_WLO, wm, wn, lane, acc);
    __syncthreads();
    stage_w(sm, NSM_WHI, NSM_WLO, 6, tid);   // sem_wv
    epi_bf16(acc, (const float*)(sm + NSM_BIAS + 1024), K0, rowBase, wm, wn, lane, BATCH);
    __syncthreads();

    mma_loop<3>(sb, NSM_AHI, NSM_ALO, NSM_WHI, NSM_WLO, wm, wn, lane, acc);
    epi_f32(acc, (const float*)(sm + NSM_BIAS + 1536), V0, rowBase, wm, wn, lane, BATCH);
}

// ===========================================================================
// Item GEMM (unchanged)
// ===========================================================================
#define ISM_A    0u
#define ISM_W    32768u
#define ISM_BIAS 65536u
#define ISMEM    66048

__global__ void __launch_bounds__(256)
gemm_item(const float* __restrict__ A,
          const unsigned short* __restrict__ W0, const unsigned short* __restrict__ W1,
          const float* __restrict__ b0, const float* __restrict__ b1,
          __nv_bfloat16* __restrict__ KV, int M)
{
    const int y = blockIdx.y;
    const unsigned short* Wt = y ? W1 : W0;
    const float* bias = y ? b1 : b0;
    __nv_bfloat16* Cb = KV + (y ? 128 : 0);

    extern __shared__ char sm[];
    const unsigned sb = smem_u32(sm);
    const int tid  = threadIdx.x;
    const int wid  = tid >> 5;
    const int lane = tid & 31;
    const int wm   = wid & 3;
    const int wn   = wid >> 2;
    const int rowBase = blockIdx.x * 128;

    if (tid < 128) ((float*)(sm + ISM_BIAS))[tid] = bias[tid];

    #pragma unroll
    for (int u = 0; u < 8; u++) {
        const int g  = u * 256 + tid;
        const int r  = g >> 4, kc = g & 15;
        int R = rowBase + r; if (R >= M) R = M - 1;
        const float4 x0 = *(const float4*)(A + (long)R * DIM + kc * 8);
        const float4 x1 = *(const float4*)(A + (long)R * DIM + kc * 8 + 4);
        const float xs[8] = {x0.x, x0.y, x0.z, x0.w, x1.x, x1.y, x1.z, x1.w};
        *(uint4*)(sm + ISM_A + sw_off(r, kc)) = pack8f16(xs);
    }
    #pragma unroll
    for (int u = 0; u < 8; u++) {
        const int g  = u * 256 + tid;
        const int n  = g >> 4, kc = g & 15;
        *(uint4*)(sm + ISM_W + sw_off(n, kc)) = *(const uint4*)(Wt + n * DIM + kc * 8);
    }
    __syncthreads();

    float acc[2][8][4];
    #pragma unroll
    for (int i = 0; i < 2; i++)
        #pragma unroll
        for (int j = 0; j < 8; j++)
            #pragma unroll
            for (int q = 0; q < 4; q++) acc[i][j][q] = 0.f;

    #pragma unroll
    for (int ks = 0; ks < 8; ks++) {
        unsigned aH[2][4], bH[8][2];
        {
            const int r  = wm * 32 + (lane & 15);
            const int kc = ks * 2 + (lane >> 4);
            ldm4(aH[0][0], aH[0][1], aH[0][2], aH[0][3], sb + ISM_A + sw_off(r,      kc));
            ldm4(aH[1][0], aH[1][1], aH[1][2], aH[1][3], sb + ISM_A + sw_off(r + 16, kc));
        }
        {
            const int grp  = lane >> 3;
            const int nloc = (lane & 7) + ((grp >> 1) << 3);
            const int kc   = ks * 2 + (grp & 1);
            #pragma unroll
            for (int j = 0; j < 4; j++) {
                const int n = wn * 64 + j * 16 + nloc;
                ldm4(bH[2*j][0], bH[2*j][1], bH[2*j+1][0], bH[2*j+1][1],
                     sb + ISM_W + sw_off(n, kc));
            }
        }
        #pragma unroll
        for (int mf = 0; mf < 2; mf++)
            #pragma unroll
            for (int nf = 0; nf < 8; nf++)
                mma_f16(acc[mf][nf], aH[mf], bH[nf]);
    }

    const float* sbias = (const float*)(sm + ISM_BIAS);
    #pragma unroll
    for (int mf = 0; mf < 2; mf++) {
        const int r0 = rowBase + wm * 32 + mf * 16 + (lane >> 2);
        #pragma unroll
        for (int nf = 0; nf < 8; nf++) {
            const int c  = wn * 64 + nf * 8 + (lane & 3) * 2;
            const float b0v = sbias[c], b1v = sbias[c + 1];
            if (r0 < M) {
                const unsigned v = pack_bf2(fmaxf(acc[mf][nf][0] + b0v, 0.f),
                                            fmaxf(acc[mf][nf][1] + b1v, 0.f));
                *(unsigned*)(Cb + (long)r0 * 256 + c) = v;
            }
            if (r0 + 8 < M) {
                const unsigned v = pack_bf2(fmaxf(acc[mf][nf][2] + b0v, 0.f),
                                            fmaxf(acc[mf][nf][3] + b1v, 0.f));
                *(unsigned*)(Cb + (long)(r0 + 8) * 256 + c) = v;
            }
        }
    }
}

// ===========================================================================
// Fused tail (unchanged from R13)
// ===========================================================================
#define TSM_AHI  0u
#define TSM_ALO  32768u
#define TSM_W1H  65536u
#define TSM_W1L  98304u
#define TSM_W2H  131072u
#define TSM_W2L  163840u
#define TSM_BIAS 196608u
#define TSM_P1   198656u
#define TSMEM    199168

__global__ void __launch_bounds__(256)
tail_fused(const float* __restrict__ Y,
           const __nv_bfloat16* __restrict__ Q2, const __nv_bfloat16* __restrict__ K0,
           const float* __restrict__ V0,
           const float* __restrict__ bo, const float* __restrict__ bk,
           const float* __restrict__ bv, const float* __restrict__ bo2,
           float* __restrict__ out)
{
    extern __shared__ char sm[];
    const unsigned sb = smem_u32(sm);
    const int tid  = threadIdx.x;
    const int wid  = tid >> 5;
    const int lane = tid & 31;
    const int wm   = wid & 3;
    const int wn   = wid >> 2;
    const int rowBase = blockIdx.x * 128;

    if (tid < 128) {
        ((float*)(sm + TSM_BIAS))[tid]        = bo[tid];
        ((float*)(sm + TSM_BIAS + 512))[tid]  = bk[tid];
        ((float*)(sm + TSM_BIAS + 1024))[tid] = bv[tid];
        ((float*)(sm + TSM_BIAS + 1536))[tid] = bo2[tid];
    }

    #pragma unroll
    for (int u = 0; u < 8; u++) {
        const int g  = u * 256 + tid;
        const int r  = g >> 4, kc = g & 15;
        const int R = rowBase + r;
        const float4 x0 = *(const float4*)(Y + (long)R * DIM + kc * 8);
        const float4 x1 = *(const float4*)(Y + (long)R * DIM + kc * 8 + 4);
        const float xs[8] = {x0.x, x0.y, x0.z, x0.w, x1.x, x1.y, x1.z, x1.w};
        uint4 H, L;
        split8(xs, H, L);
        const unsigned o = sw_off(r, kc);
        *(uint4*)(sm + TSM_AHI + o) = H;
        *(uint4*)(sm + TSM_ALO + o) = L;
    }
    stage_w(sm, TSM_W1H, TSM_W1L, 3, tid);   // gat_wo
    stage_w(sm, TSM_W2H, TSM_W2L, 5, tid);   // sem_wk
    __syncthreads();

    float acc[2][8][4];

    // phase 1: Agg
    mma_loop<3>(sb, TSM_AHI, TSM_ALO, TSM_W1H, TSM_W1L, wm, wn, lane, acc);
    __syncthreads();
    {
        const float* sbo = (const float*)(sm + TSM_BIAS);
        #pragma unroll
        for (int mf = 0; mf < 2; mf++) {
            const int r = wm * 32 + mf * 16 + (lane >> 2);
            #pragma unroll
            for (int nf = 0; nf < 8; nf++) {
                const int c  = wn * 64 + nf * 8 + (lane & 3) * 2;
                const float b0 = sbo[c], b1 = sbo[c + 1];
                store_pair_split(sm, TSM_AHI, TSM_ALO, r, c,
                                 fmaxf(acc[mf][nf][0] + b0, 0.f),
                                 fmaxf(acc[mf][nf][1] + b1, 0.f));
                store_pair_split(sm, TSM_AHI, TSM_ALO, r + 8, c,
                                 fmaxf(acc[mf][nf][2] + b0, 0.f),
                                 fmaxf(acc[mf][nf][3] + b1, 0.f));
            }
        }
    }
    stage_w(sm, TSM_W1H, TSM_W1L, 6, tid);   // sem_wv
    __syncthreads();

    // phase 2: K1 -> stash bf16 into W2H
    mma_loop<1>(sb, TSM_AHI, TSM_ALO, TSM_W2H, TSM_W2L, wm, wn, lane, acc);
    __syncthreads();
    {
        const float* sbk = (const float*)(sm + TSM_BIAS + 512);
        #pragma unroll
        for (int mf = 0; mf < 2; mf++) {
            const int r = wm * 32 + mf * 16 + (lane >> 2);
            #pragma unroll
            for (int nf = 0; nf < 8; nf++) {
                const int c  = wn * 64 + nf * 8 + (lane & 3) * 2;
                const float b0 = sbk[c], b1 = sbk[c + 1];
                *(unsigned*)(sm + TSM_W2H + r * 256 + c * 2) =
                    pack_bf2(fmaxf(acc[mf][nf][0] + b0, 0.f),
                             fmaxf(acc[mf][nf][1] + b1, 0.f));
                *(unsigned*)(sm + TSM_W2H + (r + 8) * 256 + c * 2) =
                    pack_bf2(fmaxf(acc[mf][nf][2] + b0, 0.f),
                             fmaxf(acc[mf][nf][3] + b1, 0.f));
            }
        }
    }
    __syncthreads();

    // phase 3: V1 (registers)
    mma_loop<3>(sb, TSM_AHI, TSM_ALO, TSM_W1H, TSM_W1L, wm, wn, lane, acc);

    // phase 4: per-row 2-key softmax
    {
        const float scale = 0.08838834764831845f;
        #pragma unroll
        for (int u = 0; u < 8; u++) {
            const int g  = u * 256 + tid;
            const int r  = g >> 4, cl = g & 15;
            const long base = (long)(rowBase + r) * DIM + cl * 8;

            const uint4 qu  = *(const uint4*)(Q2 + base);
            const uint4 k0u = *(const uint4*)(K0 + base);
            const uint4 k1u = *(const uint4*)(sm + TSM_W2H + r * 256 + cl * 16);

            float s0, s1;
            s0  = bflo(qu.x)*bflo(k0u.x) + bfhi(qu.x)*bfhi(k0u.x);
            s0 += bflo(qu.y)*bflo(k0u.y) + bfhi(qu.y)*bfhi(k0u.y);
            s0 += bflo(qu.z)*bflo(k0u.z) + bfhi(qu.z)*bfhi(k0u.z);
            s0 += bflo(qu.w)*bflo(k0u.w) + bfhi(qu.w)*bfhi(k0u.w);
            s1  = bflo(qu.x)*bflo(k1u.x) + bfhi(qu.x)*bfhi(k1u.x);
            s1 += bflo(qu.y)*bflo(k1u.y) + bfhi(qu.y)*bfhi(k1u.y);
            s1 += bflo(qu.z)*bflo(k1u.z) + bfhi(qu.z)*bfhi(k1u.z);
            s1 += bflo(qu.w)*bflo(k1u.w) + bfhi(qu.w)*bfhi(k1u.w);

            #pragma unroll
            for (int o = 8; o; o >>= 1) {
                s0 += __shfl_xor_sync(0xffffffffu, s0, o);
                s1 += __shfl_xor_sync(0xffffffffu, s1, o);
            }
            if (cl == 0) {
                s0 *= scale; s1 *= scale;
                const float m  = fmaxf(s0, s1);
                const float e0 = __expf(s0 - m);
                const float e1 = __expf(s1 - m);
                ((float*)(sm + TSM_P1))[r] = e1 / (e0 + e1);
            }
        }
    }
    __syncthreads();

    // phase 5: Y2 -> A slots; stage wo2
    {
        const float* sbv = (const float*)(sm + TSM_BIAS + 1024);
        const float* p1s = (const float*)(sm + TSM_P1);
        #pragma unroll
        for (int mf = 0; mf < 2; mf++) {
            const int r = wm * 32 + mf * 16 + (lane >> 2);
            #pragma unroll
            for (int nf = 0; nf < 8; nf++) {
                const int c  = wn * 64 + nf * 8 + (lane & 3) * 2;
                const float b0 = sbv[c], b1 = sbv[c + 1];
                {
                    const float p1 = p1s[r], p0 = 1.f - p1;
                    const float2 v0 = *(const float2*)(V0 + (long)(rowBase + r) * DIM + c);
                    const float v1a = fmaxf(acc[mf][nf][0] + b0, 0.f);
                    const float v1b = fmaxf(acc[mf][nf][1] + b1, 0.f);
                    store_pair_split(sm, TSM_AHI, TSM_ALO, r, c,
                                     p0 * v0.x + p1 * v1a, p0 * v0.y + p1 * v1b);
                }
                {
                    const float p1 = p1s[r + 8], p0 = 1.f - p1;
                    const float2 v0 = *(const float2*)(V0 + (long)(rowBase + r + 8) * DIM + c);
                    const float v1a = fmaxf(acc[mf][nf][2] + b0, 0.f);
                    const float v1b = fmaxf(acc[mf][nf][3] + b1, 0.f);
                    store_pair_split(sm, TSM_AHI, TSM_ALO, r + 8, c,
                                     p0 * v0.x + p1 * v1a, p0 * v0.y + p1 * v1b);
                }
            }
        }
    }
    stage_w(sm, TSM_W2H, TSM_W2L, 7, tid);   // sem_wo
    __syncthreads();

    // phase 6: out
    mma_loop<3>(sb, TSM_AHI, TSM_ALO, TSM_W2H, TSM_W2L, wm, wn, lane, acc);
    epi_f32(acc, (const float*)(sm + TSM_BIAS + 1536), out, rowBase, wm, wn, lane, BATCH);
}

// ---------------------------------------------------------------------------
// GAT attention v5: one-pass online softmax, register-capped for occupancy
// (58 regs -> <=48 via minBlocks=5; q unpacked on the fly from held uint4).
// ---------------------------------------------------------------------------
__global__ void __launch_bounds__(256, 5)
gat_attn(const __nv_bfloat16* __restrict__ Q, const int* __restrict__ movies,
         const __nv_bfloat16* __restrict__ KV, float* __restrict__ Y)
{
    const int w    = threadIdx.x >> 5;
    const int lane = threadIdx.x & 31;
    const int half = lane >> 4;
    const int cl   = lane & 15;
    const int b    = blockIdx.x * 8 + w;

    __shared__ int sidx[8][NHIST];

    if (lane < NHIST)      sidx[w][lane]      = movies[(b * NHIST + lane) * 2];
    if (lane + 32 < NHIST) sidx[w][lane + 32] = movies[(b * NHIST + lane + 32) * 2];
    __syncwarp();

    // q chunk held packed (4 regs); unpack+scale on use
    const float scale = 0.08838834764831845f;
    const uint4 qu = *(const uint4*)(Q + (long)b * DIM + cl * 8);

    float num[8];
    #pragma unroll
    for (int i = 0; i < 8; i++) num[i] = 0.f;
    float den = 0.f;

    #pragma unroll
    for (int t0 = 0; t0 < 25; t0 += 5) {
        uint4 kr[5];
        #pragma unroll
        for (int j = 0; j < 5; j++)
            kr[j] = *(const uint4*)(KV + (long)sidx[w][2*(t0+j) + half] * 256 + cl * 8);

        float sc[5];
        #pragma unroll
        for (int j = 0; j < 5; j++) {
            float s;
            s  = bflo(qu.x) * bflo(kr[j].x) + bfhi(qu.x) * bfhi(kr[j].x);
            s += bflo(qu.y) * bflo(kr[j].y) + bfhi(qu.y) * bfhi(kr[j].y);
            s += bflo(qu.z) * bflo(kr[j].z) + bfhi(qu.z) * bfhi(kr[j].z);
            s += bflo(qu.w) * bflo(kr[j].w) + bfhi(qu.w) * bfhi(kr[j].w);
            sc[j] = s * scale;
        }

        uint4 vr[5];
        #pragma unroll
        for (int j = 0; j < 5; j++)
            vr[j] = *(const uint4*)(KV + (long)sidx[w][2*(t0+j) + half] * 256 + 128 + cl * 8);

        #pragma unroll
        for (int j = 0; j < 5; j++)
            #pragma unroll
            for (int off = 8; off; off >>= 1)
                sc[j] += __shfl_xor_sync(0xffffffffu, sc[j], off);

        #pragma unroll
        for (int j = 0; j < 5; j++) {
            const float e = __expf(sc[j]);
            den += e;
            num[0] = fmaf(e, bflo(vr[j].x), num[0]);
            num[1] = fmaf(e, bfhi(vr[j].x), num[1]);
            num[2] = fmaf(e, bflo(vr[j].y), num[2]);
            num[3] = fmaf(e, bfhi(vr[j].y), num[3]);
            num[4] = fmaf(e, bflo(vr[j].z), num[4]);
            num[5] = fmaf(e, bfhi(vr[j].z), num[5]);
            num[6] = fmaf(e, bflo(vr[j].w), num[6]);
            num[7] = fmaf(e, bfhi(vr[j].w), num[7]);
        }
    }

    #pragma unroll
    for (int i = 0; i < 8; i++)
        num[i] += __shfl_xor_sync(0xffffffffu, num[i], 16);
    den += __shfl_xor_sync(0xffffffffu, den, 16);

    if (half == 0) {
        const float inv = 1.0f / den;
        *(float4*)(Y + (long)b * DIM + cl * 8) =
            make_float4(num[0]*inv, num[1]*inv, num[2]*inv, num[3]*inv);
        *(float4*)(Y + (long)b * DIM + cl * 8 + 4) =
            make_float4(num[4]*inv, num[5]*inv, num[6]*inv, num[7]*inv);
    }
}

// ---------------------------------------------------------------------------
// Host launcher (5 launches, single stream — R13 ordering restored)
// ---------------------------------------------------------------------------
extern "C" void kernel_launch(void* const* d_in, const int* in_sizes, int n_in,
                              void* d_out, int out_size)
{
    const int*   uids       = (const int*)  d_in[0];
    const int*   u_movies   = (const int*)  d_in[2];
    const float* user_table = (const float*)d_in[3];
    const float* item_table = (const float*)d_in[5];
    const float* gat_wq = (const float*)d_in[6],  *gat_bq = (const float*)d_in[7];
    const float* gat_wk = (const float*)d_in[8],  *gat_bk = (const float*)d_in[9];
    const float* gat_wv = (const float*)d_in[10], *gat_bv = (const float*)d_in[11];
    const float* gat_wo = (const float*)d_in[12], *gat_bo = (const float*)d_in[13];
    const float* sem_wq = (const float*)d_in[14], *sem_bq = (const float*)d_in[15];
    const float* sem_wk = (const float*)d_in[16], *sem_bk = (const float*)d_in[17];
    const float* sem_wv = (const float*)d_in[18], *sem_bv = (const float*)d_in[19];
    const float* sem_wo = (const float*)d_in[20], *sem_bo = (const float*)d_in[21];
    float* out = (float*)d_out;

    __nv_bfloat16 *KV, *Qg, *Q2, *K0;
    unsigned short *Wh0, *Wh1;
    float *V0, *Y;
    cudaGetSymbolAddress((void**)&KV,  g_KV);
    cudaGetSymbolAddress((void**)&Qg,  g_Qg);
    cudaGetSymbolAddress((void**)&Q2,  g_Q2);
    cudaGetSymbolAddress((void**)&K0,  g_K0);
    cudaGetSymbolAddress((void**)&V0,  g_V0);
    cudaGetSymbolAddress((void**)&Y,   g_Y);
    {
        void* p;
        cudaGetSymbolAddress(&p, g_Wh);
        Wh0 = (unsigned short*)p;
        Wh1 = Wh0 + DIM * DIM;
    }

    static bool attr_done = false;
    if (!attr_done) {
        cudaFuncSetAttribute(node_all,   cudaFuncAttributeMaxDynamicSharedMemorySize, NSMEM);
        cudaFuncSetAttribute(gemm_item,  cudaFuncAttributeMaxDynamicSharedMemorySize, ISMEM);
        cudaFuncSetAttribute(tail_fused, cudaFuncAttributeMaxDynamicSharedMemorySize, TSMEM);
        attr_done = true;
    }

    const dim3 blk(256);
    const int gItems = (NITEMS + 127) / 128;     // 782
    const int gBatch = BATCH / 128;              // 128

    // 0: weight transpose + splits
    w_setup<<<64, 256>>>(gat_wq, gat_wk, gat_wv, gat_wo,
                         sem_wq, sem_wk, sem_wv, sem_wo);

    // 1: node transforms (Qg/Q2/K0 bf16, V0 fp32)
    node_all<<<gBatch, blk, NSMEM>>>(user_table, uids,
                                     gat_bq, sem_bq, sem_bk, sem_bv,
                                     Qg, Q2, K0, V0);

    // 2: item K/V -> bf16 KV table
    gemm_item<<<dim3(gItems, 2), blk, ISMEM>>>(item_table, Wh0, Wh1,
                                               gat_bk, gat_bv, KV, NITEMS);

    // 3: GAT attention (register-capped for occupancy)
    gat_attn<<<BATCH / 8, blk>>>(Qg, u_movies, KV, Y);

    // 4: fused tail
    tail_fused<<<gBatch, blk, TSMEM>>>(Y, Q2, K0, V0,
                                       gat_bo, sem_bk, sem_bv, sem_bo, out);
}